// round 1
// baseline (speedup 1.0000x reference)
#include <cuda_runtime.h>
#include <cuda_bf16.h>
#include <math.h>

// ---------------- problem constants ----------------
#define NT      32768          // B*N nodes
#define NGRAPH  16
#define NPER    2048           // nodes per graph
#define IN_C    256
#define DIM     128
#define H1DIM   256            // 2*DIM
#define NATOMS  20
#define ENC_H   100
#define OUTC    6
#define MASK_WORDS (NT * 64)   // NT rows x 2048 bits / 32

// ---------------- scratch (no allocation allowed) ----------------
__device__ float    g_h1[NT * H1DIM];      // 33.5 MB
__device__ float    g_h2[NT * DIM];        // 16.8 MB
__device__ float    g_t1[NT * 128];        // 16.8 MB (padded 100->128)
__device__ unsigned g_mask[MASK_WORDS];    // 8.4 MB adjacency bitmask
__device__ float    g_stats[2 * IN_C];     // sums / sumsq
__device__ int      g_ids[NT];
__device__ float    g_W1f[IN_C * H1DIM];   // BN-folded W1
__device__ float    g_b1f[H1DIM];
__device__ float    g_TW[NATOMS * DIM];    // embed[0:20] @ W_msg
__device__ float    g_A1p[128 * 128];      // A1 padded to 128 cols
__device__ float    g_a1p[128];

__device__ __forceinline__ float gelu(float x) {
    return 0.5f * x * (1.0f + erff(x * 0.70710678118654752f));
}

// ---------------- K0: zero accumulators ----------------
__global__ void k_zero() {
    int i = blockIdx.x * blockDim.x + threadIdx.x;   // 4096 x 512 = 2097152
    if (i < MASK_WORDS) g_mask[i] = 0u;
    if (i < 2 * IN_C)   g_stats[i] = 0.0f;
}

// ---------------- K1: BN stats (sum, sumsq per channel) ----------------
__global__ void k_bn_stats(const float* __restrict__ x) {
    int c  = threadIdx.x;                 // 256 threads = channels
    int r0 = blockIdx.x * 128;            // 256 blocks * 128 rows
    float s = 0.f, q = 0.f;
    #pragma unroll 4
    for (int r = 0; r < 128; r++) {
        float v = x[(size_t)(r0 + r) * IN_C + c];
        s += v; q += v * v;
    }
    atomicAdd(&g_stats[c], s);
    atomicAdd(&g_stats[IN_C + c], q);
}

// ---------------- K2: fold BN into W1 ----------------
__global__ void k_fold(const float* __restrict__ W1, const float* __restrict__ b1,
                       const float* __restrict__ gamma, const float* __restrict__ beta) {
    int j = blockIdx.x;      // output col, 256 blocks
    int c = threadIdx.x;     // input channel, 256 threads
    float mean = g_stats[c] * (1.0f / NT);
    float var  = g_stats[IN_C + c] * (1.0f / NT) - mean * mean;
    float inv  = rsqrtf(var + 1e-5f);
    float sc   = gamma[c] * inv;
    float sh   = beta[c] - mean * sc;
    float w    = W1[c * H1DIM + j];
    g_W1f[c * H1DIM + j] = sc * w;
    __shared__ float red[256];
    red[c] = sh * w;
    __syncthreads();
    for (int o = 128; o > 0; o >>= 1) {
        if (c < o) red[c] += red[c + o];
        __syncthreads();
    }
    if (c == 0) g_b1f[j] = b1[j] + red[0];
}

// ---------------- K3: TW = embed[0:20] @ W_msg ----------------
__global__ void k_tw(const float* __restrict__ embed, const float* __restrict__ Wm) {
    int t = blockIdx.x * blockDim.x + threadIdx.x;  // 10 x 256 = 2560
    if (t < NATOMS * DIM) {
        int a = t >> 7, j = t & 127;
        float s = 0.f;
        #pragma unroll 8
        for (int d = 0; d < DIM; d++) s += embed[a * DIM + d] * Wm[d * DIM + j];
        g_TW[t] = s;
    }
}

// ---------------- K3b: pad A1 (128x100 -> 128x128) ----------------
__global__ void k_padA1(const float* __restrict__ A1, const float* __restrict__ a1) {
    int t = blockIdx.x * blockDim.x + threadIdx.x;  // 64 x 256 = 16384
    if (t < 128 * 128) {
        int k = t >> 7, j = t & 127;
        g_A1p[t] = (j < ENC_H) ? A1[k * ENC_H + j] : 0.0f;
        if (k == 0) g_a1p[j] = (j < ENC_H) ? a1[j] : 0.0f;
    }
}

// ---------------- K4: edge scatter into adjacency bitmask ----------------
__global__ void k_edges(const int* __restrict__ ei, int E) {
    int e = blockIdx.x * blockDim.x + threadIdx.x;
    if (e < E) {
        int s = ei[e];
        int d = ei[E + e];
        if ((s >> 11) == (d >> 11)) {                 // intra-graph only
            unsigned bit = ((unsigned)s << 11) + (unsigned)(d & (NPER - 1));
            atomicOr(&g_mask[bit >> 5], 1u << (bit & 31));
        }
    }
}

// ---------------- tiled SGEMM + bias + gelu (BM=BN=128, BK=8, TM=TN=8) ----------------
__global__ void __launch_bounds__(256)
k_sgemm_gelu(const float* __restrict__ A, const float* __restrict__ B,
             const float* __restrict__ bias, float* __restrict__ C,
             int K, int N) {
    __shared__ float As[8][128];
    __shared__ float Bs[8][128];
    int tid = threadIdx.x;
    const float* Ab = A + (size_t)blockIdx.y * 128 * K;
    const float* Bb = B + blockIdx.x * 128;
    float*       Cb = C + (size_t)blockIdx.y * 128 * N + blockIdx.x * 128;
    const float* bb = bias + blockIdx.x * 128;

    int arow = tid >> 1, acol = (tid & 1) * 4;
    int brow = tid >> 5, bcol = (tid & 31) * 4;
    int tr = (tid >> 4) * 8, tc = (tid & 15) * 8;

    float acc[8][8];
    #pragma unroll
    for (int i = 0; i < 8; i++)
        #pragma unroll
        for (int j = 0; j < 8; j++) acc[i][j] = 0.f;

    for (int k0 = 0; k0 < K; k0 += 8) {
        float4 av = *(const float4*)(Ab + (size_t)arow * K + k0 + acol);
        As[acol + 0][arow] = av.x; As[acol + 1][arow] = av.y;
        As[acol + 2][arow] = av.z; As[acol + 3][arow] = av.w;
        float4 bv = *(const float4*)(Bb + (size_t)(k0 + brow) * N + bcol);
        *(float4*)&Bs[brow][bcol] = bv;
        __syncthreads();
        #pragma unroll
        for (int kk = 0; kk < 8; kk++) {
            float ra[8], rb[8];
            #pragma unroll
            for (int i = 0; i < 8; i++) ra[i] = As[kk][tr + i];
            #pragma unroll
            for (int j = 0; j < 8; j++) rb[j] = Bs[kk][tc + j];
            #pragma unroll
            for (int i = 0; i < 8; i++)
                #pragma unroll
                for (int j = 0; j < 8; j++) acc[i][j] += ra[i] * rb[j];
        }
        __syncthreads();
    }
    #pragma unroll
    for (int i = 0; i < 8; i++) {
        int row = tr + i;
        float o[8];
        #pragma unroll
        for (int j = 0; j < 8; j++) o[j] = gelu(acc[i][j] + bb[tc + j]);
        *(float4*)(Cb + (size_t)row * N + tc)     = make_float4(o[0], o[1], o[2], o[3]);
        *(float4*)(Cb + (size_t)row * N + tc + 4) = make_float4(o[4], o[5], o[6], o[7]);
    }
}

// ---------------- K7: logits (h2 @ W3 + b3) + argmax -> ids ----------------
__global__ void __launch_bounds__(256)
k_logits_argmax(const float* __restrict__ W3, const float* __restrict__ b3) {
    __shared__ float rows[64][129];
    __shared__ float W3s[128 * NATOMS];
    __shared__ float b3s[NATOMS];
    int tid = threadIdx.x;
    int rbase = blockIdx.x * 64;

    const float* src = g_h2 + (size_t)rbase * DIM;
    for (int i = tid; i < 64 * 128; i += 256) rows[i >> 7][i & 127] = src[i];
    for (int i = tid; i < 128 * NATOMS; i += 256) W3s[i] = W3[i];
    if (tid < NATOMS) b3s[tid] = b3[tid];
    __syncthreads();

    int r = tid >> 2, part = tid & 3;   // 4 threads/row, 5 cols each
    float acc[5] = {0, 0, 0, 0, 0};
    for (int k = 0; k < 128; k++) {
        float v = rows[r][k];
        #pragma unroll
        for (int j = 0; j < 5; j++) acc[j] += v * W3s[k * NATOMS + part * 5 + j];
    }
    float best = -1e30f; int bidx = 0;
    #pragma unroll
    for (int j = 0; j < 5; j++) {
        int col = part * 5 + j;
        float lg = acc[j] + b3s[col];
        if (lg > best) { best = lg; bidx = col; }
    }
    #pragma unroll
    for (int o = 1; o <= 2; o <<= 1) {
        float v2 = __shfl_xor_sync(0xffffffffu, best, o);
        int   i2 = __shfl_xor_sync(0xffffffffu, bidx, o);
        if (v2 > best || (v2 == best && i2 < bidx)) { best = v2; bidx = i2; }
    }
    if (part == 0) g_ids[rbase + r] = bidx;
}

// ---------------- K8: aggregation (hist over neighbor ids) -> hout = z, coords ----------------
__global__ void __launch_bounds__(256)
k_agg(const float* __restrict__ b_msg, const float* __restrict__ w_coor,
      const float* __restrict__ coords, float* __restrict__ out_z,
      float* __restrict__ out_coors) {
    __shared__ float TWs[NATOMS * DIM];
    __shared__ float wcs[DIM * 3];
    __shared__ float bms[DIM];
    __shared__ int   hist[8][NATOMS];
    int tid = threadIdx.x;
    for (int i = tid; i < NATOMS * DIM; i += 256) TWs[i] = g_TW[i];
    for (int i = tid; i < DIM * 3; i += 256)      wcs[i] = w_coor[i];
    for (int i = tid; i < DIM; i += 256)          bms[i] = b_msg[i];
    __syncthreads();

    int warp = tid >> 5, lane = tid & 31;
    int* myhist = hist[warp];
    int wglobal = blockIdx.x * 8 + warp;
    int wstride = gridDim.x * 8;
    int d0 = lane * 4;

    for (int node = wglobal; node < NT; node += wstride) {
        if (lane < NATOMS) myhist[lane] = 0;
        __syncwarp();
        int base = node & ~(NPER - 1);
        int deg = 0;
        #pragma unroll
        for (int half = 0; half < 2; half++) {
            int w = lane + half * 32;
            unsigned m = g_mask[(size_t)node * 64 + w];
            deg += __popc(m);
            while (m) {
                int b = __ffs(m) - 1;
                m &= m - 1;
                int id = g_ids[base + w * 32 + b];
                atomicAdd(&myhist[id], 1);
            }
        }
        deg = __reduce_add_sync(0xffffffffu, deg);
        __syncwarp();
        float invdeg = 1.0f / (float)(deg > 0 ? deg : 1);
        int myid = g_ids[node];

        float4 s = make_float4(0.f, 0.f, 0.f, 0.f);
        #pragma unroll
        for (int a = 0; a < NATOMS; a++) {
            float c = (float)myhist[a];
            float4 t = *(const float4*)&TWs[a * DIM + d0];
            s.x += c * t.x; s.y += c * t.y; s.z += c * t.z; s.w += c * t.w;
        }
        float4 own = *(const float4*)&TWs[myid * DIM + d0];
        float h0 = gelu(bms[d0 + 0] + own.x + invdeg * s.x);
        float h1 = gelu(bms[d0 + 1] + own.y + invdeg * s.y);
        float h2 = gelu(bms[d0 + 2] + own.z + invdeg * s.z);
        float h3 = gelu(bms[d0 + 3] + own.w + invdeg * s.w);
        *(float4*)&out_z[(size_t)node * DIM + d0] = make_float4(h0, h1, h2, h3);

        // coords: 3 dots of 128
        float p0 = h0 * wcs[(d0 + 0) * 3 + 0] + h1 * wcs[(d0 + 1) * 3 + 0]
                 + h2 * wcs[(d0 + 2) * 3 + 0] + h3 * wcs[(d0 + 3) * 3 + 0];
        float p1 = h0 * wcs[(d0 + 0) * 3 + 1] + h1 * wcs[(d0 + 1) * 3 + 1]
                 + h2 * wcs[(d0 + 2) * 3 + 1] + h3 * wcs[(d0 + 3) * 3 + 1];
        float p2 = h0 * wcs[(d0 + 0) * 3 + 2] + h1 * wcs[(d0 + 1) * 3 + 2]
                 + h2 * wcs[(d0 + 2) * 3 + 2] + h3 * wcs[(d0 + 3) * 3 + 2];
        #pragma unroll
        for (int o = 16; o > 0; o >>= 1) {
            p0 += __shfl_xor_sync(0xffffffffu, p0, o);
            p1 += __shfl_xor_sync(0xffffffffu, p1, o);
            p2 += __shfl_xor_sync(0xffffffffu, p2, o);
        }
        if (lane == 0) {
            out_coors[(size_t)node * 3 + 0] = coords[(size_t)node * 3 + 0] + tanhf(p0);
            out_coors[(size_t)node * 3 + 1] = coords[(size_t)node * 3 + 1] + tanhf(p1);
            out_coors[(size_t)node * 3 + 2] = coords[(size_t)node * 3 + 2] + tanhf(p2);
        }
    }
}

// ---------------- K10: t1 -> t2 -> DynamicTanh -> angles ----------------
__global__ void __launch_bounds__(256)
k_angles(const float* __restrict__ A2, const float* __restrict__ a2,
         const float* __restrict__ dyt_alpha, const float* __restrict__ dyt_w,
         const float* __restrict__ dyt_b, float* __restrict__ out_angles) {
    __shared__ float rows[64][129];
    __shared__ float A2s[ENC_H * OUTC];
    __shared__ float a2s[OUTC];
    int tid = threadIdx.x;
    int rbase = blockIdx.x * 64;
    const float* src = g_t1 + (size_t)rbase * 128;
    for (int i = tid; i < 64 * 128; i += 256) rows[i >> 7][i & 127] = src[i];
    for (int i = tid; i < ENC_H * OUTC; i += 256) A2s[i] = A2[i];
    if (tid < OUTC) a2s[tid] = a2[tid];
    __syncthreads();

    if (tid < 64) {
        float alpha = dyt_alpha[0];
        float acc[OUTC] = {0, 0, 0, 0, 0, 0};
        for (int k = 0; k < ENC_H; k++) {
            float v = rows[tid][k];
            #pragma unroll
            for (int c = 0; c < OUTC; c++) acc[c] += v * A2s[k * OUTC + c];
        }
        int node = rbase + tid;
        #pragma unroll
        for (int c = 0; c < OUTC; c++) {
            float t = gelu(acc[c] + a2s[c]);
            float u = tanhf(alpha * t) * dyt_w[c] + dyt_b[c];
            out_angles[(size_t)node * OUTC + c] = tanhf(u);
        }
    }
}

// ---------------- launch ----------------
extern "C" void kernel_launch(void* const* d_in, const int* in_sizes, int n_in,
                              void* d_out, int out_size) {
    const float* x_res     = (const float*)d_in[0];
    const float* coords    = (const float*)d_in[1];
    const int*   edge_idx  = (const int*)  d_in[2];
    // d_in[3] = batch (implied by node id / 2048)
    const float* bn_gamma  = (const float*)d_in[4];
    const float* bn_beta   = (const float*)d_in[5];
    const float* W1        = (const float*)d_in[6];
    const float* b1        = (const float*)d_in[7];
    const float* W2        = (const float*)d_in[8];
    const float* b2        = (const float*)d_in[9];
    const float* W3        = (const float*)d_in[10];
    const float* b3        = (const float*)d_in[11];
    const float* embed     = (const float*)d_in[12];
    const float* W_msg     = (const float*)d_in[13];
    const float* b_msg     = (const float*)d_in[14];
    const float* w_coor    = (const float*)d_in[15];
    const float* A1        = (const float*)d_in[16];
    const float* a1        = (const float*)d_in[17];
    const float* A2        = (const float*)d_in[18];
    const float* a2        = (const float*)d_in[19];
    const float* dyt_alpha = (const float*)d_in[20];
    const float* dyt_w     = (const float*)d_in[21];
    const float* dyt_b     = (const float*)d_in[22];
    int E = in_sizes[2] / 2;

    float* out        = (float*)d_out;
    float* out_angles = out;                       // NT*6
    float* out_z      = out + (size_t)NT * OUTC;   // NT*128
    float* out_coors  = out_z + (size_t)NT * DIM;  // NT*3

    float* h1p;  cudaGetSymbolAddress((void**)&h1p,  g_h1);
    float* h2p;  cudaGetSymbolAddress((void**)&h2p,  g_h2);
    float* t1p;  cudaGetSymbolAddress((void**)&t1p,  g_t1);
    float* W1fp; cudaGetSymbolAddress((void**)&W1fp, g_W1f);
    float* b1fp; cudaGetSymbolAddress((void**)&b1fp, g_b1f);
    float* A1pp; cudaGetSymbolAddress((void**)&A1pp, g_A1p);
    float* a1pp; cudaGetSymbolAddress((void**)&a1pp, g_a1p);

    k_zero<<<4096, 512>>>();
    k_bn_stats<<<NT / 128, 256>>>(x_res);
    k_fold<<<H1DIM, IN_C>>>(W1, b1, bn_gamma, bn_beta);
    k_tw<<<10, 256>>>(embed, W_msg);
    k_padA1<<<64, 256>>>(A1, a1);
    k_edges<<<(E + 255) / 256, 256>>>(edge_idx, E);

    // h1 = gelu(xn @ W1 + b1)  [32768 x 256]
    k_sgemm_gelu<<<dim3(H1DIM / 128, NT / 128), 256>>>(x_res, W1fp, b1fp, h1p, IN_C, H1DIM);
    // h2 = gelu(h1 @ W2 + b2)  [32768 x 128]
    k_sgemm_gelu<<<dim3(DIM / 128, NT / 128), 256>>>(h1p, W2, b2, h2p, H1DIM, DIM);
    // ids = argmax(h2 @ W3 + b3)
    k_logits_argmax<<<NT / 64, 256>>>(W3, b3);
    // hout -> z, coords
    k_agg<<<512, 256>>>(b_msg, w_coor, coords, out_z, out_coors);
    // t1 = gelu(z @ A1p + a1p)  [32768 x 128 padded]
    k_sgemm_gelu<<<dim3(1, NT / 128), 256>>>(out_z, A1pp, a1pp, t1p, DIM, 128);
    // angles
    k_angles<<<NT / 64, 256>>>(A2, a2, dyt_alpha, dyt_w, dyt_b, out_angles);
}